// round 5
// baseline (speedup 1.0000x reference)
#include <cuda_runtime.h>
#include <cstdint>

// SpaceLoss2: loss = mean(relu(||f - proto[lab]||^2 - ||f - f[argmin_masked(f@f^T)]||^2 + 0.5))
// B=4096, D=256, NUM_IDS=100000.
//
// Plan:
//   k0: init scratch (+detect label dtype int32 vs int64)
//   k1: fused SGEMM(ftr @ ftr^T) + per-row masked argmin via packed u64 atomicMin
//   k2: per-row loss (gather proto + neg, squared distances, relu)
//   k3: deterministic tree-reduction -> mean -> d_out[0]

#define D      256
#define MAXB   4096
#define MARGIN 0.5f

#define BM 128
#define BN 128
#define BK 32
#define TM 8
#define TN 8

__device__ unsigned long long g_neg[MAXB];   // packed (ordered-float key << 32) | col
__device__ float              g_loss[MAXB];
__device__ int                g_lab64;       // 1 if labels are int64, 0 if int32

// monotone float -> uint mapping (handles negatives)
__device__ __forceinline__ unsigned int f2ord(float f) {
    unsigned int u = __float_as_uint(f);
    return (u & 0x80000000u) ? ~u : (u | 0x80000000u);
}

__device__ __forceinline__ int get_label(const void* lab, int i) {
    if (g_lab64) return (int)((const long long*)lab)[i];
    return ((const int*)lab)[i];
}

// ---------------------------------------------------------------------------
__global__ void init_kernel(float* out, const int* lab_words, int B) {
    int i = blockIdx.x * blockDim.x + threadIdx.x;
    if (i < B) g_neg[i] = 0xFFFFFFFFFFFFFFFFull;
    if (i == 0) {
        out[0] = 0.0f;
        // dtype sniff: if int64, every odd 32-bit word (high half) is 0
        // (labels are nonneg < 100000). For int32 data this is ~impossible.
        int zeros = 0;
        #pragma unroll 1
        for (int k = 0; k < 64; k++)
            if (lab_words[2 * k + 1] == 0) zeros++;
        g_lab64 = (zeros == 64) ? 1 : 0;
    }
}

// ---------------------------------------------------------------------------
// Fused sim-tile GEMM + masked row-argmin.
// Each block: 128x128 tile of sim = ftr[rows] @ ftr[cols]^T, K=256 in 8 chunks of 32.
__global__ __launch_bounds__(256, 2)
void simmin_kernel(const float* __restrict__ ftr, const void* __restrict__ label, int B) {
    __shared__ float As[BK][BM];
    __shared__ float Bs[BK][BN];
    __shared__ int   labs[BM];

    const int rowBase = blockIdx.y * BM;
    const int colBase = blockIdx.x * BN;
    const int tid = threadIdx.x;
    const int tx  = tid & 15;       // 0..15
    const int ty  = tid >> 4;       // 0..15

    if (tid < BM) labs[tid] = get_label(label, rowBase + tid);

    // global load mapping: thread -> (row within tile, which half of the 32-wide K chunk)
    const int lrow  = tid >> 1;            // 0..127
    const int lc4   = (tid & 1) * 4;       // float4 slot base: 0 or 4

    const float* aG = ftr + (size_t)(rowBase + lrow) * D;
    const float* bG = ftr + (size_t)(colBase + lrow) * D;

    float4 aR[4], bR[4];
    #pragma unroll
    for (int i = 0; i < 4; i++) {
        aR[i] = *(const float4*)(aG + (lc4 + i) * 4);
        bR[i] = *(const float4*)(bG + (lc4 + i) * 4);
    }

    float acc[TM][TN];
    #pragma unroll
    for (int i = 0; i < TM; i++)
        #pragma unroll
        for (int j = 0; j < TN; j++) acc[i][j] = 0.0f;

    // store chunk 0
    #pragma unroll
    for (int i = 0; i < 4; i++) {
        int k = (lc4 + i) * 4;
        As[k + 0][lrow] = aR[i].x; As[k + 1][lrow] = aR[i].y;
        As[k + 2][lrow] = aR[i].z; As[k + 3][lrow] = aR[i].w;
        Bs[k + 0][lrow] = bR[i].x; Bs[k + 1][lrow] = bR[i].y;
        Bs[k + 2][lrow] = bR[i].z; Bs[k + 3][lrow] = bR[i].w;
    }
    __syncthreads();

    const int NKT = D / BK;  // 8
    #pragma unroll 1
    for (int kt = 0; kt < NKT; kt++) {
        // prefetch next chunk into registers (overlaps with compute below)
        if (kt + 1 < NKT) {
            int ko = (kt + 1) * BK;
            #pragma unroll
            for (int i = 0; i < 4; i++) {
                aR[i] = *(const float4*)(aG + ko + (lc4 + i) * 4);
                bR[i] = *(const float4*)(bG + ko + (lc4 + i) * 4);
            }
        }
        // compute on current smem tiles
        #pragma unroll
        for (int k = 0; k < BK; k++) {
            float4 a0 = *(const float4*)&As[k][ty * TM];
            float4 a1 = *(const float4*)&As[k][ty * TM + 4];
            float4 b0 = *(const float4*)&Bs[k][tx * TN];
            float4 b1 = *(const float4*)&Bs[k][tx * TN + 4];
            float a[TM] = {a0.x, a0.y, a0.z, a0.w, a1.x, a1.y, a1.z, a1.w};
            float b[TN] = {b0.x, b0.y, b0.z, b0.w, b1.x, b1.y, b1.z, b1.w};
            #pragma unroll
            for (int i = 0; i < TM; i++)
                #pragma unroll
                for (int j = 0; j < TN; j++)
                    acc[i][j] = fmaf(a[i], b[j], acc[i][j]);
        }
        __syncthreads();
        if (kt + 1 < NKT) {
            #pragma unroll
            for (int i = 0; i < 4; i++) {
                int k = (lc4 + i) * 4;
                As[k + 0][lrow] = aR[i].x; As[k + 1][lrow] = aR[i].y;
                As[k + 2][lrow] = aR[i].z; As[k + 3][lrow] = aR[i].w;
                Bs[k + 0][lrow] = bR[i].x; Bs[k + 1][lrow] = bR[i].y;
                Bs[k + 2][lrow] = bR[i].z; Bs[k + 3][lrow] = bR[i].w;
            }
            __syncthreads();
        }
    }

    // masked per-row min over this thread's 8 columns, packed (orderkey, col)
    unsigned long long best[TM];
    #pragma unroll
    for (int i = 0; i < TM; i++) {
        best[i] = 0xFFFFFFFFFFFFFFFFull;
        const int lab = labs[ty * TM + i];
        #pragma unroll
        for (int j = 0; j < TN; j++) {
            int c = colBase + tx * TN + j;
            unsigned long long key =
                ((unsigned long long)f2ord(acc[i][j]) << 32) | (unsigned int)c;
            if (c != lab) best[i] = min(best[i], key);
        }
    }
    // reduce across tx (16 lanes; xor stays inside the 16-lane half-warp)
    #pragma unroll
    for (int off = 8; off > 0; off >>= 1) {
        #pragma unroll
        for (int i = 0; i < TM; i++) {
            unsigned long long o = __shfl_xor_sync(0xFFFFFFFFu, best[i], off);
            best[i] = min(best[i], o);
        }
    }
    if (tx == 0) {
        #pragma unroll
        for (int i = 0; i < TM; i++)
            atomicMin(&g_neg[rowBase + ty * TM + i], best[i]);
    }
}

// ---------------------------------------------------------------------------
// One block (64 threads) per row: pos/neg squared distances -> relu loss.
__global__ void loss_kernel(const float* __restrict__ ftr,
                            const float* __restrict__ proto,
                            const void* __restrict__ label, int B) {
    __shared__ float sp[2], sn[2];
    const int r = blockIdx.x;
    const int t = threadIdx.x;  // 0..63, each handles one float4 of D=256

    const int lab  = get_label(label, r);
    const int negc = (int)(unsigned int)(g_neg[r] & 0xFFFFFFFFull);

    float4 a = ((const float4*)(ftr   + (size_t)r    * D))[t];
    float4 y = ((const float4*)(proto + (size_t)lab  * D))[t];
    float4 n = ((const float4*)(ftr   + (size_t)negc * D))[t];

    float dx, pd, nd;
    dx = a.x - y.x; pd  = dx * dx;
    dx = a.y - y.y; pd += dx * dx;
    dx = a.z - y.z; pd += dx * dx;
    dx = a.w - y.w; pd += dx * dx;
    dx = a.x - n.x; nd  = dx * dx;
    dx = a.y - n.y; nd += dx * dx;
    dx = a.z - n.z; nd += dx * dx;
    dx = a.w - n.w; nd += dx * dx;

    #pragma unroll
    for (int off = 16; off > 0; off >>= 1) {
        pd += __shfl_xor_sync(0xFFFFFFFFu, pd, off);
        nd += __shfl_xor_sync(0xFFFFFFFFu, nd, off);
    }
    if ((t & 31) == 0) { sp[t >> 5] = pd; sn[t >> 5] = nd; }
    __syncthreads();
    if (t == 0) {
        float P = sp[0] + sp[1];
        float N = sn[0] + sn[1];
        g_loss[r] = fmaxf(P - N + MARGIN, 0.0f);
    }
}

// ---------------------------------------------------------------------------
__global__ void reduce_kernel(float* out, int B) {
    __shared__ float s[256];
    const int t = threadIdx.x;
    float v = 0.0f;
    for (int i = t; i < B; i += 256) v += g_loss[i];
    s[t] = v;
    __syncthreads();
    #pragma unroll
    for (int off = 128; off > 0; off >>= 1) {
        if (t < off) s[t] += s[t + off];
        __syncthreads();
    }
    if (t == 0) out[0] = s[0] / (float)B;
}

// ---------------------------------------------------------------------------
extern "C" void kernel_launch(void* const* d_in, const int* in_sizes, int n_in,
                              void* d_out, int out_size) {
    const float* ftr   = (const float*)d_in[0];
    // d_in[1] = teachor_ftr (unused by the reference computation)
    const float* proto = (const float*)d_in[2];
    const void*  label = d_in[3];
    const int B = in_sizes[3];          // 4096 (label element count)
    float* out = (float*)d_out;

    init_kernel<<<(B + 255) / 256, 256>>>(out, (const int*)label, B);

    dim3 grid(B / BN, B / BM);          // 32 x 32
    simmin_kernel<<<grid, 256>>>(ftr, label, B);

    loss_kernel<<<B, 64>>>(ftr, proto, label, B);
    reduce_kernel<<<1, 256>>>(out, B);
}

// round 9
// speedup vs baseline: 1.5603x; 1.5603x over previous
#include <cuda_runtime.h>
#include <cstdint>

// SpaceLoss2 on GB300 (sm_103; tcgen05 unavailable at compute_103):
//   - symmetric sim matrix: only lower-triangular 128x128 tiles (528/1024)
//   - fma.rn.f32x2 packed dual-FMA (2x FP32 rate, sm_100-family base PTX)
//   - off-diag tiles feed argmin of their row band AND (transposed) col band
//   - static __shared__ only (26 KB), no dynamic-smem opt-in, no static guards
//   k0: init (g_neg, out, label dtype sniff)
//   k1: triangular simmin GEMM (f32x2) -> packed u64 atomicMin per row
//   k2: per-row exact fp32 loss
//   k3: deterministic tree reduce -> mean

#define D      256
#define MAXB   4096
#define MARGIN 0.5f

#define BM 128
#define BN 128
#define BK 16
#define TM 8
#define TN 8

__device__ unsigned long long g_neg[MAXB];   // packed (ordered-float key << 32) | col
__device__ float              g_loss[MAXB];
__device__ int                g_lab64;

// packed dual fp32 FMA: d = a * b + d (elementwise on 2-lane packs)
#define FMA2(d, a, b) \
    asm("fma.rn.f32x2 %0, %1, %2, %0;" : "+l"(d) : "l"(a), "l"(b))

// monotone float -> uint mapping (handles negatives)
__device__ __forceinline__ unsigned int f2ord(float f) {
    unsigned int u = __float_as_uint(f);
    return (u & 0x80000000u) ? ~u : (u | 0x80000000u);
}

__device__ __forceinline__ int get_label(const void* lab, int i) {
    if (g_lab64) return (int)((const long long*)lab)[i];
    return ((const int*)lab)[i];
}

// ---------------------------------------------------------------------------
__global__ void init_kernel(float* out, const int* lab_words, int B) {
    int i = blockIdx.x * blockDim.x + threadIdx.x;
    if (i < B) g_neg[i] = 0xFFFFFFFFFFFFFFFFull;
    if (i == 0) {
        out[0] = 0.0f;
        // dtype sniff: int64 labels (< 100000, nonneg) -> all high words zero.
        int zeros = 0;
        #pragma unroll 1
        for (int k = 0; k < 64; k++)
            if (lab_words[2 * k + 1] == 0) zeros++;
        g_lab64 = (zeros == 64) ? 1 : 0;
    }
}

// ---------------------------------------------------------------------------
// Triangular fused GEMM + masked argmin (rows and, for off-diag, columns).
__global__ __launch_bounds__(256, 2)
void simmin_kernel(const float* __restrict__ ftr, const void* __restrict__ label, int B) {
    __shared__ float AsD[BK][2 * BM];                 // A duplicated: 16 KB
    __shared__ float Bs[BK][BN];                      // 8 KB
    __shared__ int   labR[BM];
    __shared__ int   labC[BM];
    __shared__ unsigned long long cmin[BM];

    // triangular block decode: bid -> (bi >= bj)
    const int bid = blockIdx.x;
    float tq = sqrtf(8.0f * (float)bid + 1.0f);
    int bi = (int)((tq - 1.0f) * 0.5f);
    while ((bi + 1) * (bi + 2) / 2 <= bid) bi++;
    while (bi * (bi + 1) / 2 > bid) bi--;
    const int bj = bid - bi * (bi + 1) / 2;

    const int rowBase = bi * BM;
    const int colBase = bj * BN;
    const int tid = threadIdx.x;
    const int tx  = tid & 15;        // 0..15 -> col group
    const int ty  = tid >> 4;        // 0..15 -> row group
    const bool offdiag = (bi != bj);

    if (tid < BM) {
        labR[tid] = get_label(label, rowBase + tid);
        labC[tid] = get_label(label, colBase + tid);
        cmin[tid] = 0xFFFFFFFFFFFFFFFFull;
    }

    // global load mapping: thread -> (row within tile, half of the 16-wide K chunk)
    const int lrow = tid >> 1;            // 0..127
    const int lk   = (tid & 1) * 8;       // k offset within chunk: 0 or 8

    const float* aG = ftr + (size_t)(rowBase + lrow) * D + lk;
    const float* bG = ftr + (size_t)(colBase + lrow) * D + lk;

    float4 aR[2], bR[2];
    #pragma unroll
    for (int i = 0; i < 2; i++) {
        aR[i] = *(const float4*)(aG + i * 4);
        bR[i] = *(const float4*)(bG + i * 4);
    }

    unsigned long long acc2[TM][TN / 2];
    #pragma unroll
    for (int i = 0; i < TM; i++)
        #pragma unroll
        for (int j = 0; j < TN / 2; j++) acc2[i][j] = 0ull;

    const int NKT = D / BK;  // 16
    #pragma unroll 1
    for (int kt = 0; kt < NKT; kt++) {
        // store current chunk (A duplicated per element, B plain)
        #pragma unroll
        for (int i = 0; i < 2; i++) {
            float va[4] = {aR[i].x, aR[i].y, aR[i].z, aR[i].w};
            float vb[4] = {bR[i].x, bR[i].y, bR[i].z, bR[i].w};
            #pragma unroll
            for (int c = 0; c < 4; c++) {
                int k = lk + i * 4 + c;
                *(float2*)&AsD[k][2 * lrow] = make_float2(va[c], va[c]);
                Bs[k][lrow] = vb[c];
            }
        }
        __syncthreads();
        // prefetch next chunk
        if (kt + 1 < NKT) {
            int ko = (kt + 1) * BK;
            #pragma unroll
            for (int i = 0; i < 2; i++) {
                aR[i] = *(const float4*)(aG + ko + i * 4);
                bR[i] = *(const float4*)(bG + ko + i * 4);
            }
        }
        // compute on current smem tiles
        #pragma unroll
        for (int k = 0; k < BK; k++) {
            unsigned long long a2[TM], b2[TN / 2];
            const unsigned long long* ap =
                (const unsigned long long*)&AsD[k][2 * (ty * TM)];
            const unsigned long long* bp =
                (const unsigned long long*)&Bs[k][tx * TN];
            #pragma unroll
            for (int i = 0; i < TM; i++) a2[i] = ap[i];
            #pragma unroll
            for (int j = 0; j < TN / 2; j++) b2[j] = bp[j];
            #pragma unroll
            for (int i = 0; i < TM; i++)
                #pragma unroll
                for (int j = 0; j < TN / 2; j++)
                    FMA2(acc2[i][j], a2[i], b2[j]);
        }
        __syncthreads();
    }

    // ---- epilogue: row-band argmin (sim[rowBase+r][colBase+c]) -------------
    #pragma unroll
    for (int i = 0; i < TM; i++) {
        const int lab = labR[ty * TM + i];
        unsigned long long best = 0xFFFFFFFFFFFFFFFFull;
        #pragma unroll
        for (int j = 0; j < TN; j++) {
            int c = colBase + tx * TN + j;
            float v = ((const float*)&acc2[i][j >> 1])[j & 1];
            unsigned long long key =
                ((unsigned long long)f2ord(v) << 32) | (unsigned int)c;
            if (c != lab) best = min(best, key);
        }
        // reduce across tx (xor stays within 16-lane halves of the warp)
        #pragma unroll
        for (int off = 8; off > 0; off >>= 1) {
            unsigned long long o = __shfl_xor_sync(0xFFFFFFFFu, best, off);
            best = min(best, o);
        }
        if (tx == 0) atomicMin(&g_neg[rowBase + ty * TM + i], best);
    }

    // ---- epilogue: transposed col-band argmin (off-diagonal tiles) ---------
    if (offdiag) {
        #pragma unroll
        for (int j = 0; j < TN; j++) {
            const int rp  = tx * TN + j;            // local sim-row in col band
            const int lab = labC[rp];
            unsigned long long best = 0xFFFFFFFFFFFFFFFFull;
            #pragma unroll
            for (int i = 0; i < TM; i++) {
                int cp = rowBase + ty * TM + i;     // candidate col = global row
                float v = ((const float*)&acc2[i][j >> 1])[j & 1];
                unsigned long long key =
                    ((unsigned long long)f2ord(v) << 32) | (unsigned int)cp;
                if (cp != lab) best = min(best, key);
            }
            // fold the two ty values in this warp (lane xor 16 flips ty bit0)
            unsigned long long o = __shfl_xor_sync(0xFFFFFFFFu, best, 16);
            best = min(best, o);
            if ((tid & 16) == 0) atomicMin(&cmin[rp], best);
        }
        __syncthreads();
        if (tid < BN) atomicMin(&g_neg[colBase + tid], cmin[tid]);
    }
}

// ---------------------------------------------------------------------------
// One block (64 threads) per row: exact fp32 pos/neg distances -> relu loss.
__global__ void loss_kernel(const float* __restrict__ ftr,
                            const float* __restrict__ proto,
                            const void* __restrict__ label, int B) {
    __shared__ float sp[2], sn[2];
    const int r = blockIdx.x;
    const int t = threadIdx.x;  // 0..63, one float4 of D=256 each

    const int lab  = get_label(label, r);
    const int negc = (int)(unsigned int)(g_neg[r] & 0xFFFFFFFFull);

    float4 a = ((const float4*)(ftr   + (size_t)r    * D))[t];
    float4 y = ((const float4*)(proto + (size_t)lab  * D))[t];
    float4 n = ((const float4*)(ftr   + (size_t)negc * D))[t];

    float dx, pd, nd;
    dx = a.x - y.x; pd  = dx * dx;
    dx = a.y - y.y; pd += dx * dx;
    dx = a.z - y.z; pd += dx * dx;
    dx = a.w - y.w; pd += dx * dx;
    dx = a.x - n.x; nd  = dx * dx;
    dx = a.y - n.y; nd += dx * dx;
    dx = a.z - n.z; nd += dx * dx;
    dx = a.w - n.w; nd += dx * dx;

    #pragma unroll
    for (int off = 16; off > 0; off >>= 1) {
        pd += __shfl_xor_sync(0xFFFFFFFFu, pd, off);
        nd += __shfl_xor_sync(0xFFFFFFFFu, nd, off);
    }
    if ((t & 31) == 0) { sp[t >> 5] = pd; sn[t >> 5] = nd; }
    __syncthreads();
    if (t == 0) {
        float P = sp[0] + sp[1];
        float N = sn[0] + sn[1];
        g_loss[r] = fmaxf(P - N + MARGIN, 0.0f);
    }
}

// ---------------------------------------------------------------------------
__global__ void reduce_kernel(float* out, int B) {
    __shared__ float s[256];
    const int t = threadIdx.x;
    float v = 0.0f;
    for (int i = t; i < B; i += 256) v += g_loss[i];
    s[t] = v;
    __syncthreads();
    #pragma unroll
    for (int off = 128; off > 0; off >>= 1) {
        if (t < off) s[t] += s[t + off];
        __syncthreads();
    }
    if (t == 0) out[0] = s[0] / (float)B;
}

// ---------------------------------------------------------------------------
extern "C" void kernel_launch(void* const* d_in, const int* in_sizes, int n_in,
                              void* d_out, int out_size) {
    const float* ftr   = (const float*)d_in[0];
    // d_in[1] = teachor_ftr (unused by the reference computation)
    const float* proto = (const float*)d_in[2];
    const void*  label = d_in[3];
    const int B = in_sizes[3];          // 4096
    float* out = (float*)d_out;

    init_kernel<<<(B + 255) / 256, 256>>>(out, (const int*)label, B);

    const int NT = B / BM;                       // 32
    const int nblocks = NT * (NT + 1) / 2;       // 528
    simmin_kernel<<<nblocks, 256>>>(ftr, label, B);

    loss_kernel<<<B, 64>>>(ftr, proto, label, B);
    reduce_kernel<<<1, 256>>>(out, B);
}